// round 9
// baseline (speedup 1.0000x reference)
#include <cuda_runtime.h>
#include <cuda_bf16.h>
#include <cstdint>

// LSTMNet: B=1024, T=2048, H=64, NC=10
// CTA = 256 threads handles TWO batch elements (grid 512).
// Thread t: hid = t>>2, gate = t&3 (0=i,1=f,2=g,3=o), row r = gate*64+hid.
// W_hh row in 32 packed u64 regs, SHARED between both batch streams.
// Activations via MUFU.TANH (tanh.approx.f32); sigma(z)=0.5*tanh(z/2)+0.5.
// Cell update + tanh(c) + h store done ONLY by the gate==3 lane of each quad.
// One __syncthreads per timestep covering both batch streams.

#define T_LEN 2048
#define HDIM  64
#define NCLS  10

#define FMA2(acc, a, b) \
    asm("fma.rn.f32x2 %0, %1, %2, %0;" : "+l"(acc) : "l"(a), "l"(b))
#define ADD2(d, a, b) \
    asm("add.rn.f32x2 %0, %1, %2;" : "=l"(d) : "l"(a), "l"(b))

__device__ __forceinline__ float tanh_fast(float z) {
    float r;
    asm("tanh.approx.f32 %0, %1;" : "=f"(r) : "f"(z));
    return r;
}

__global__ __launch_bounds__(256, 2)
void lstm_net_kernel(const float* __restrict__ x,
                     const float* __restrict__ W_ih,
                     const float* __restrict__ W_hh,
                     const float* __restrict__ b_ih,
                     const float* __restrict__ b_hh,
                     const float* __restrict__ fc1_w,
                     const float* __restrict__ fc1_b,
                     const float* __restrict__ fc2_w,
                     const float* __restrict__ fc2_b,
                     float* __restrict__ out)
{
    __shared__ __align__(16) float sxA[T_LEN];     // batch elem A's x row (8 KB)
    __shared__ __align__(16) float sxB[T_LEN];     // batch elem B's x row (8 KB)
    __shared__ __align__(16) float shA[2][HDIM];   // double-buffered hidden, A
    __shared__ __align__(16) float shB[2][HDIM];   // double-buffered hidden, B
    __shared__ __align__(16) float s1A[HDIM];      // fc1 out A
    __shared__ __align__(16) float s1B[HDIM];      // fc1 out B

    const int bA   = 2 * blockIdx.x;
    const int bB   = bA + 1;
    const int t    = threadIdx.x;
    const int hid  = t >> 2;
    const int gate = t & 3;
    const int r    = gate * HDIM + hid;            // row in the 4H-stacked params

    // ---- stage x rows into smem (coalesced float4) ----
    {
        const float4* xA = reinterpret_cast<const float4*>(x + (size_t)bA * T_LEN);
        const float4* xB = reinterpret_cast<const float4*>(x + (size_t)bB * T_LEN);
        float4* sA4 = reinterpret_cast<float4*>(sxA);
        float4* sB4 = reinterpret_cast<float4*>(sxB);
        #pragma unroll
        for (int i = t; i < T_LEN / 4; i += 256) { sA4[i] = xA[i]; sB4[i] = xB[i]; }
    }

    // ---- W_hh row -> 32 packed (f32,f32) registers (shared across both streams) ----
    unsigned long long wp[32];
    {
        const ulonglong2* wrow = reinterpret_cast<const ulonglong2*>(W_hh + (size_t)r * HDIM);
        #pragma unroll
        for (int q = 0; q < 16; q++) {
            ulonglong2 v = wrow[q];
            wp[2 * q]     = v.x;
            wp[2 * q + 1] = v.y;
        }
    }
    const float w_in = W_ih[r];
    const float bias = b_ih[r] + b_hh[r];

    // branchless activation: sigmoid(z) = 0.5*tanh(0.5z)+0.5 ; gate 2 uses tanh(z)
    const float zs = (gate == 2) ? 1.0f : 0.5f;
    const float aa = (gate == 2) ? 1.0f : 0.5f;
    const float ab = (gate == 2) ? 0.0f : 0.5f;
    const bool  owner = (gate == 3);               // lane holding o does the cell update

    if (t < HDIM) shA[0][t] = 0.0f;
    else if (t < 2 * HDIM) shB[0][t - HDIM] = 0.0f;
    float cA = 0.0f, cB = 0.0f;
    __syncthreads();

    #pragma unroll 1
    for (int step = 0; step < T_LEN; step++) {
        const int p  = step & 1;
        const int np = p ^ 1;

        const float preA = fmaf(sxA[step], w_in, bias);
        const float preB = fmaf(sxB[step], w_in, bias);

        unsigned long long aA0 = (unsigned long long)__float_as_uint(preA);
        unsigned long long aB0 = (unsigned long long)__float_as_uint(preB);
        unsigned long long aA1 = 0ull, aA2 = 0ull, aA3 = 0ull;
        unsigned long long aB1 = 0ull, aB2 = 0ull, aB3 = 0ull;

        const ulonglong2* hpA = reinterpret_cast<const ulonglong2*>(shA[p]);
        const ulonglong2* hpB = reinterpret_cast<const ulonglong2*>(shB[p]);

        #pragma unroll 4
        for (int q = 0; q < 16; q++) {
            ulonglong2 vA = hpA[q];                // LDS.128 broadcast
            ulonglong2 vB = hpB[q];
            if (q & 1) {
                FMA2(aA2, wp[2 * q],     vA.x);
                FMA2(aA3, wp[2 * q + 1], vA.y);
                FMA2(aB2, wp[2 * q],     vB.x);
                FMA2(aB3, wp[2 * q + 1], vB.y);
            } else {
                FMA2(aA0, wp[2 * q],     vA.x);
                FMA2(aA1, wp[2 * q + 1], vA.y);
                FMA2(aB0, wp[2 * q],     vB.x);
                FMA2(aB1, wp[2 * q + 1], vB.y);
            }
        }

        unsigned long long sA01, sA23, sA, sB01, sB23, sB;
        ADD2(sA01, aA0, aA1);  ADD2(sA23, aA2, aA3);  ADD2(sA, sA01, sA23);
        ADD2(sB01, aB0, aB1);  ADD2(sB23, aB2, aB3);  ADD2(sB, sB01, sB23);
        const float gsA = __uint_as_float((unsigned)sA) + __uint_as_float((unsigned)(sA >> 32));
        const float gsB = __uint_as_float((unsigned)sB) + __uint_as_float((unsigned)(sB >> 32));

        // one MUFU.TANH per gate per stream
        const float actA = fmaf(tanh_fast(gsA * zs), aa, ab);
        const float actB = fmaf(tanh_fast(gsB * zs), aa, ab);

        // gather i, f, g into the quad's o-lane (lane 3 of each quad)
        const float iA = __shfl_sync(0xffffffffu, actA, 0, 4);
        const float fA = __shfl_sync(0xffffffffu, actA, 1, 4);
        const float gA = __shfl_sync(0xffffffffu, actA, 2, 4);
        const float iB = __shfl_sync(0xffffffffu, actB, 0, 4);
        const float fB = __shfl_sync(0xffffffffu, actB, 1, 4);
        const float gB = __shfl_sync(0xffffffffu, actB, 2, 4);

        if (owner) {
            cA = fmaf(fA, cA, iA * gA);
            cB = fmaf(fB, cB, iB * gB);
            shA[np][hid] = actA * tanh_fast(cA);   // actA = sigmoid(o) here
            shB[np][hid] = actB * tanh_fast(cB);
        }
        __syncthreads();
    }

    // T_LEN even: final h lives in buffer 0
    const float* hfA = shA[0];
    const float* hfB = shB[0];

    // ---- fc1 + relu: threads 0..63 do A, 64..127 do B ----
    if (t < HDIM) {
        float a = fc1_b[t];
        const float* wr = fc1_w + t * HDIM;
        #pragma unroll 16
        for (int k = 0; k < HDIM; k++) a = fmaf(wr[k], hfA[k], a);
        s1A[t] = fmaxf(a, 0.0f);
    } else if (t < 2 * HDIM) {
        const int j = t - HDIM;
        float a = fc1_b[j];
        const float* wr = fc1_w + j * HDIM;
        #pragma unroll 16
        for (int k = 0; k < HDIM; k++) a = fmaf(wr[k], hfB[k], a);
        s1B[j] = fmaxf(a, 0.0f);
    }
    __syncthreads();

    // ---- fc2: threads 0..9 do A, 64..73 do B ----
    if (t < NCLS) {
        float a = fc2_b[t];
        const float* wr = fc2_w + t * HDIM;
        #pragma unroll 16
        for (int k = 0; k < HDIM; k++) a = fmaf(wr[k], s1A[k], a);
        out[(size_t)bA * NCLS + t] = a;
    } else if (t >= HDIM && t < HDIM + NCLS) {
        const int j = t - HDIM;
        float a = fc2_b[j];
        const float* wr = fc2_w + j * HDIM;
        #pragma unroll 16
        for (int k = 0; k < HDIM; k++) a = fmaf(wr[k], s1B[k], a);
        out[(size_t)bB * NCLS + j] = a;
    }
}

extern "C" void kernel_launch(void* const* d_in, const int* in_sizes, int n_in,
                              void* d_out, int out_size)
{
    const float* x     = (const float*)d_in[0];
    const float* W_ih  = (const float*)d_in[1];
    const float* W_hh  = (const float*)d_in[2];
    const float* b_ih  = (const float*)d_in[3];
    const float* b_hh  = (const float*)d_in[4];
    const float* fc1_w = (const float*)d_in[5];
    const float* fc1_b = (const float*)d_in[6];
    const float* fc2_w = (const float*)d_in[7];
    const float* fc2_b = (const float*)d_in[8];
    float* out = (float*)d_out;

    const int B = in_sizes[0] / T_LEN;   // 1024

    lstm_net_kernel<<<B / 2, 256>>>(x, W_ih, W_hh, b_ih, b_hh,
                                    fc1_w, fc1_b, fc2_w, fc2_b, out);
}

// round 10
// speedup vs baseline: 1.0027x; 1.0027x over previous
#include <cuda_runtime.h>
#include <cuda_bf16.h>
#include <cstdint>

// LSTMNet: B=1024, T=2048, H=64, NC=10
// CTA = 256 threads handles TWO batch elements (grid 512).
// Thread t: hid = t>>2, gate = t&3 (0=i,1=f,2=g,3=o), row r = gate*64+hid.
// W_hh row in 32 packed u64 regs, SHARED between both batch streams.
// Activations via MUFU.TANH (tanh.approx.f32); sigma(z)=0.5*tanh(z/2)+0.5.
// Cell update + tanh(c) + h store done ONLY by the gate==3 lane of each quad.
// One __syncthreads per timestep covering both batch streams.

#define T_LEN 2048
#define HDIM  64
#define NCLS  10

#define FMA2(acc, a, b) \
    asm("fma.rn.f32x2 %0, %1, %2, %0;" : "+l"(acc) : "l"(a), "l"(b))
#define ADD2(d, a, b) \
    asm("add.rn.f32x2 %0, %1, %2;" : "=l"(d) : "l"(a), "l"(b))

__device__ __forceinline__ float tanh_fast(float z) {
    float r;
    asm("tanh.approx.f32 %0, %1;" : "=f"(r) : "f"(z));
    return r;
}

__global__ __launch_bounds__(256, 2)
void lstm_net_kernel(const float* __restrict__ x,
                     const float* __restrict__ W_ih,
                     const float* __restrict__ W_hh,
                     const float* __restrict__ b_ih,
                     const float* __restrict__ b_hh,
                     const float* __restrict__ fc1_w,
                     const float* __restrict__ fc1_b,
                     const float* __restrict__ fc2_w,
                     const float* __restrict__ fc2_b,
                     float* __restrict__ out)
{
    __shared__ __align__(16) float sxA[T_LEN];     // batch elem A's x row (8 KB)
    __shared__ __align__(16) float sxB[T_LEN];     // batch elem B's x row (8 KB)
    __shared__ __align__(16) float shA[2][HDIM];   // double-buffered hidden, A
    __shared__ __align__(16) float shB[2][HDIM];   // double-buffered hidden, B
    __shared__ __align__(16) float s1A[HDIM];      // fc1 out A
    __shared__ __align__(16) float s1B[HDIM];      // fc1 out B

    const int bA   = 2 * blockIdx.x;
    const int bB   = bA + 1;
    const int t    = threadIdx.x;
    const int hid  = t >> 2;
    const int gate = t & 3;
    const int r    = gate * HDIM + hid;            // row in the 4H-stacked params

    // ---- stage x rows into smem (coalesced float4) ----
    {
        const float4* xA = reinterpret_cast<const float4*>(x + (size_t)bA * T_LEN);
        const float4* xB = reinterpret_cast<const float4*>(x + (size_t)bB * T_LEN);
        float4* sA4 = reinterpret_cast<float4*>(sxA);
        float4* sB4 = reinterpret_cast<float4*>(sxB);
        #pragma unroll
        for (int i = t; i < T_LEN / 4; i += 256) { sA4[i] = xA[i]; sB4[i] = xB[i]; }
    }

    // ---- W_hh row -> 32 packed (f32,f32) registers (shared across both streams) ----
    unsigned long long wp[32];
    {
        const ulonglong2* wrow = reinterpret_cast<const ulonglong2*>(W_hh + (size_t)r * HDIM);
        #pragma unroll
        for (int q = 0; q < 16; q++) {
            ulonglong2 v = wrow[q];
            wp[2 * q]     = v.x;
            wp[2 * q + 1] = v.y;
        }
    }
    const float w_in = W_ih[r];
    const float bias = b_ih[r] + b_hh[r];

    // branchless activation: sigmoid(z) = 0.5*tanh(0.5z)+0.5 ; gate 2 uses tanh(z)
    const float zs = (gate == 2) ? 1.0f : 0.5f;
    const float aa = (gate == 2) ? 1.0f : 0.5f;
    const float ab = (gate == 2) ? 0.0f : 0.5f;
    const bool  owner = (gate == 3);               // lane holding o does the cell update

    if (t < HDIM) shA[0][t] = 0.0f;
    else if (t < 2 * HDIM) shB[0][t - HDIM] = 0.0f;
    float cA = 0.0f, cB = 0.0f;
    __syncthreads();

    #pragma unroll 1
    for (int step = 0; step < T_LEN; step++) {
        const int p  = step & 1;
        const int np = p ^ 1;

        const float preA = fmaf(sxA[step], w_in, bias);
        const float preB = fmaf(sxB[step], w_in, bias);

        unsigned long long aA0 = (unsigned long long)__float_as_uint(preA);
        unsigned long long aB0 = (unsigned long long)__float_as_uint(preB);
        unsigned long long aA1 = 0ull, aA2 = 0ull, aA3 = 0ull;
        unsigned long long aB1 = 0ull, aB2 = 0ull, aB3 = 0ull;

        const ulonglong2* hpA = reinterpret_cast<const ulonglong2*>(shA[p]);
        const ulonglong2* hpB = reinterpret_cast<const ulonglong2*>(shB[p]);

        #pragma unroll 4
        for (int q = 0; q < 16; q++) {
            ulonglong2 vA = hpA[q];                // LDS.128 broadcast
            ulonglong2 vB = hpB[q];
            if (q & 1) {
                FMA2(aA2, wp[2 * q],     vA.x);
                FMA2(aA3, wp[2 * q + 1], vA.y);
                FMA2(aB2, wp[2 * q],     vB.x);
                FMA2(aB3, wp[2 * q + 1], vB.y);
            } else {
                FMA2(aA0, wp[2 * q],     vA.x);
                FMA2(aA1, wp[2 * q + 1], vA.y);
                FMA2(aB0, wp[2 * q],     vB.x);
                FMA2(aB1, wp[2 * q + 1], vB.y);
            }
        }

        unsigned long long sA01, sA23, sA, sB01, sB23, sB;
        ADD2(sA01, aA0, aA1);  ADD2(sA23, aA2, aA3);  ADD2(sA, sA01, sA23);
        ADD2(sB01, aB0, aB1);  ADD2(sB23, aB2, aB3);  ADD2(sB, sB01, sB23);
        const float gsA = __uint_as_float((unsigned)sA) + __uint_as_float((unsigned)(sA >> 32));
        const float gsB = __uint_as_float((unsigned)sB) + __uint_as_float((unsigned)(sB >> 32));

        // one MUFU.TANH per gate per stream
        const float actA = fmaf(tanh_fast(gsA * zs), aa, ab);
        const float actB = fmaf(tanh_fast(gsB * zs), aa, ab);

        // gather i, f, g into the quad's o-lane (lane 3 of each quad)
        const float iA = __shfl_sync(0xffffffffu, actA, 0, 4);
        const float fA = __shfl_sync(0xffffffffu, actA, 1, 4);
        const float gA = __shfl_sync(0xffffffffu, actA, 2, 4);
        const float iB = __shfl_sync(0xffffffffu, actB, 0, 4);
        const float fB = __shfl_sync(0xffffffffu, actB, 1, 4);
        const float gB = __shfl_sync(0xffffffffu, actB, 2, 4);

        if (owner) {
            cA = fmaf(fA, cA, iA * gA);
            cB = fmaf(fB, cB, iB * gB);
            shA[np][hid] = actA * tanh_fast(cA);   // actA = sigmoid(o) here
            shB[np][hid] = actB * tanh_fast(cB);
        }
        __syncthreads();
    }

    // T_LEN even: final h lives in buffer 0
    const float* hfA = shA[0];
    const float* hfB = shB[0];

    // ---- fc1 + relu: threads 0..63 do A, 64..127 do B ----
    if (t < HDIM) {
        float a = fc1_b[t];
        const float* wr = fc1_w + t * HDIM;
        #pragma unroll 16
        for (int k = 0; k < HDIM; k++) a = fmaf(wr[k], hfA[k], a);
        s1A[t] = fmaxf(a, 0.0f);
    } else if (t < 2 * HDIM) {
        const int j = t - HDIM;
        float a = fc1_b[j];
        const float* wr = fc1_w + j * HDIM;
        #pragma unroll 16
        for (int k = 0; k < HDIM; k++) a = fmaf(wr[k], hfB[k], a);
        s1B[j] = fmaxf(a, 0.0f);
    }
    __syncthreads();

    // ---- fc2: threads 0..9 do A, 64..73 do B ----
    if (t < NCLS) {
        float a = fc2_b[t];
        const float* wr = fc2_w + t * HDIM;
        #pragma unroll 16
        for (int k = 0; k < HDIM; k++) a = fmaf(wr[k], s1A[k], a);
        out[(size_t)bA * NCLS + t] = a;
    } else if (t >= HDIM && t < HDIM + NCLS) {
        const int j = t - HDIM;
        float a = fc2_b[j];
        const float* wr = fc2_w + j * HDIM;
        #pragma unroll 16
        for (int k = 0; k < HDIM; k++) a = fmaf(wr[k], s1B[k], a);
        out[(size_t)bB * NCLS + j] = a;
    }
}

extern "C" void kernel_launch(void* const* d_in, const int* in_sizes, int n_in,
                              void* d_out, int out_size)
{
    const float* x     = (const float*)d_in[0];
    const float* W_ih  = (const float*)d_in[1];
    const float* W_hh  = (const float*)d_in[2];
    const float* b_ih  = (const float*)d_in[3];
    const float* b_hh  = (const float*)d_in[4];
    const float* fc1_w = (const float*)d_in[5];
    const float* fc1_b = (const float*)d_in[6];
    const float* fc2_w = (const float*)d_in[7];
    const float* fc2_b = (const float*)d_in[8];
    float* out = (float*)d_out;

    const int B = in_sizes[0] / T_LEN;   // 1024

    lstm_net_kernel<<<B / 2, 256>>>(x, W_ih, W_hh, b_ih, b_hh,
                                    fc1_w, fc1_b, fc2_w, fc2_b, out);
}

// round 11
// speedup vs baseline: 1.6896x; 1.6850x over previous
#include <cuda_runtime.h>
#include <cuda_bf16.h>
#include <cstdint>

// LSTMNet: B=1024, T=2048, H=64, NC=10
// One CTA per batch element, 256 threads.
// Quad-split-K layout: thread (hid = t>>2, q = t&3) holds the K-chunk
// [16q, 16q+16) of ALL FOUR gate rows of its hid (4 x 16 weights = 32 u64 regs).
// Per step: 4 LDS.128 (vs 16 in row-per-thread layout), 32 FMA2, then a
// 2-round quad butterfly puts gate q's full preactivation in lane q.
// Activations via MUFU.TANH; cell update replicated across the quad (free at
// warp granularity); lane q==0 stores h. One __syncthreads per timestep.

#define T_LEN 2048
#define HDIM  64
#define NCLS  10

#define FMA2(acc, a, b) \
    asm("fma.rn.f32x2 %0, %1, %2, %0;" : "+l"(acc) : "l"(a), "l"(b))

__device__ __forceinline__ float tanh_fast(float z) {
    float r;
    asm("tanh.approx.f32 %0, %1;" : "=f"(r) : "f"(z));
    return r;
}

__device__ __forceinline__ float pair_sum(unsigned long long a) {
    return __uint_as_float((unsigned)a) + __uint_as_float((unsigned)(a >> 32));
}

__global__ __launch_bounds__(256, 2)
void lstm_net_kernel(const float* __restrict__ x,
                     const float* __restrict__ W_ih,
                     const float* __restrict__ W_hh,
                     const float* __restrict__ b_ih,
                     const float* __restrict__ b_hh,
                     const float* __restrict__ fc1_w,
                     const float* __restrict__ fc1_b,
                     const float* __restrict__ fc2_w,
                     const float* __restrict__ fc2_b,
                     float* __restrict__ out)
{
    __shared__ __align__(16) float sx[T_LEN];      // x row (8 KB)
    __shared__ __align__(16) float sh[2][HDIM];    // double-buffered hidden
    __shared__ __align__(16) float s1[HDIM];       // fc1 out

    const int b   = blockIdx.x;
    const int t   = threadIdx.x;
    const int hid = t >> 2;
    const int q   = t & 3;                          // K-chunk / owned-gate index
    const int r   = q * HDIM + hid;                 // row whose activation lane owns

    // ---- stage x[b,:] (coalesced float4) ----
    {
        const float4* xr = reinterpret_cast<const float4*>(x + (size_t)b * T_LEN);
        float4* sx4 = reinterpret_cast<float4*>(sx);
        #pragma unroll
        for (int i = t; i < T_LEN / 4; i += 256) sx4[i] = xr[i];
    }

    // ---- weights: 4 gate rows of hid, chunk [16q,16q+16) -> 32 u64 regs ----
    unsigned long long w[4][8];
    #pragma unroll
    for (int g = 0; g < 4; g++) {
        const ulonglong2* wr =
            reinterpret_cast<const ulonglong2*>(W_hh + (size_t)(g * HDIM + hid) * HDIM + 16 * q);
        #pragma unroll
        for (int j = 0; j < 4; j++) {
            ulonglong2 v = wr[j];
            w[g][2 * j]     = v.x;
            w[g][2 * j + 1] = v.y;
        }
    }
    const float w_in = W_ih[r];
    const float bias = b_ih[r] + b_hh[r];

    // branchless activation: sigmoid(z)=0.5*tanh(0.5z)+0.5 ; gate 2 uses tanh
    const float zs = (q == 2) ? 1.0f : 0.5f;
    const float aa = (q == 2) ? 1.0f : 0.5f;
    const float ab = (q == 2) ? 0.0f : 0.5f;
    const bool  par = (q & 1);                      // butterfly round-1 parity
    const bool  hi2 = (q >> 1);                     // butterfly round-2 half

    if (t < HDIM) sh[0][t] = 0.0f;
    float c = 0.0f;
    __syncthreads();

    // one LSTM step: read sh[RB], write sh[RB^1]
    #define LSTM_STEP(RB, XT)                                                        \
    {                                                                                \
        const ulonglong2* hp = reinterpret_cast<const ulonglong2*>(sh[RB]) + 4 * q;  \
        ulonglong2 h0 = hp[0], h1 = hp[1], h2 = hp[2], h3 = hp[3];                   \
        unsigned long long a0 = 0ull, a1 = 0ull, a2 = 0ull, a3 = 0ull;               \
        FMA2(a0, w[0][0], h0.x); FMA2(a1, w[1][0], h0.x);                            \
        FMA2(a2, w[2][0], h0.x); FMA2(a3, w[3][0], h0.x);                            \
        FMA2(a0, w[0][1], h0.y); FMA2(a1, w[1][1], h0.y);                            \
        FMA2(a2, w[2][1], h0.y); FMA2(a3, w[3][1], h0.y);                            \
        FMA2(a0, w[0][2], h1.x); FMA2(a1, w[1][2], h1.x);                            \
        FMA2(a2, w[2][2], h1.x); FMA2(a3, w[3][2], h1.x);                            \
        FMA2(a0, w[0][3], h1.y); FMA2(a1, w[1][3], h1.y);                            \
        FMA2(a2, w[2][3], h1.y); FMA2(a3, w[3][3], h1.y);                            \
        FMA2(a0, w[0][4], h2.x); FMA2(a1, w[1][4], h2.x);                            \
        FMA2(a2, w[2][4], h2.x); FMA2(a3, w[3][4], h2.x);                            \
        FMA2(a0, w[0][5], h2.y); FMA2(a1, w[1][5], h2.y);                            \
        FMA2(a2, w[2][5], h2.y); FMA2(a3, w[3][5], h2.y);                            \
        FMA2(a0, w[0][6], h3.x); FMA2(a1, w[1][6], h3.x);                            \
        FMA2(a2, w[2][6], h3.x); FMA2(a3, w[3][6], h3.x);                            \
        FMA2(a0, w[0][7], h3.y); FMA2(a1, w[1][7], h3.y);                            \
        FMA2(a2, w[2][7], h3.y); FMA2(a3, w[3][7], h3.y);                            \
        float s0 = pair_sum(a0), s1v = pair_sum(a1);                                 \
        float s2 = pair_sum(a2), s3v = pair_sum(a3);                                 \
        /* quad butterfly: lane q ends with full sum of gate q */                    \
        float k0 = par ? s1v : s0;                                                   \
        float k1 = par ? s3v : s2;                                                   \
        float e0 = par ? s0 : s1v;                                                   \
        float e1 = par ? s2 : s3v;                                                   \
        k0 += __shfl_xor_sync(0xffffffffu, e0, 1, 4);                                \
        k1 += __shfl_xor_sync(0xffffffffu, e1, 1, 4);                                \
        float keep = hi2 ? k1 : k0;                                                  \
        float send = hi2 ? k0 : k1;                                                  \
        float S = keep + __shfl_xor_sync(0xffffffffu, send, 2, 4);                   \
        float gsum = fmaf((XT), w_in, bias) + S;                                     \
        float act = fmaf(tanh_fast(gsum * zs), aa, ab);                              \
        float iv = __shfl_sync(0xffffffffu, act, 0, 4);                              \
        float fv = __shfl_sync(0xffffffffu, act, 1, 4);                              \
        float gv = __shfl_sync(0xffffffffu, act, 2, 4);                              \
        float ov = __shfl_sync(0xffffffffu, act, 3, 4);                              \
        c = fmaf(fv, c, iv * gv);                                                    \
        float hnew = ov * tanh_fast(c);                                              \
        if (q == 0) sh[(RB) ^ 1][hid] = hnew;                                        \
        __syncthreads();                                                             \
    }

    #pragma unroll 1
    for (int step = 0; step < T_LEN; step += 4) {
        const float4 xv = *reinterpret_cast<const float4*>(&sx[step]);
        LSTM_STEP(0, xv.x)
        LSTM_STEP(1, xv.y)
        LSTM_STEP(0, xv.z)
        LSTM_STEP(1, xv.w)
    }
    #undef LSTM_STEP

    // T_LEN % 4 == 0: final h lives in sh[0]
    const float* hf = sh[0];

    // ---- fc1 + relu (64 threads) ----
    if (t < HDIM) {
        float a = fc1_b[t];
        const float* wr = fc1_w + t * HDIM;
        #pragma unroll 16
        for (int k = 0; k < HDIM; k++) a = fmaf(wr[k], hf[k], a);
        s1[t] = fmaxf(a, 0.0f);
    }
    __syncthreads();

    // ---- fc2 (10 threads) ----
    if (t < NCLS) {
        float a = fc2_b[t];
        const float* wr = fc2_w + t * HDIM;
        #pragma unroll 16
        for (int k = 0; k < HDIM; k++) a = fmaf(wr[k], s1[k], a);
        out[(size_t)b * NCLS + t] = a;
    }
}

extern "C" void kernel_launch(void* const* d_in, const int* in_sizes, int n_in,
                              void* d_out, int out_size)
{
    const float* x     = (const float*)d_in[0];
    const float* W_ih  = (const float*)d_in[1];
    const float* W_hh  = (const float*)d_in[2];
    const float* b_ih  = (const float*)d_in[3];
    const float* b_hh  = (const float*)d_in[4];
    const float* fc1_w = (const float*)d_in[5];
    const float* fc1_b = (const float*)d_in[6];
    const float* fc2_w = (const float*)d_in[7];
    const float* fc2_b = (const float*)d_in[8];
    float* out = (float*)d_out;

    const int B = in_sizes[0] / T_LEN;   // 1024

    lstm_net_kernel<<<B, 256>>>(x, W_ih, W_hh, b_ih, b_hh,
                                fc1_w, fc1_b, fc2_w, fc2_b, out);
}

// round 12
// speedup vs baseline: 3.0621x; 1.8124x over previous
#include <cuda_runtime.h>
#include <cuda_bf16.h>
#include <cstdint>

// LSTMNet: B=1024, T=2048, H=64, NC=10
// 128-thread CTA per batch element, 3 CTAs/SM (3 independent recurrence streams).
// Thread (hid = t>>1, p = t&1): p=0 owns gate rows {i,f} of hid, p=1 owns {g,o}.
// Each thread holds BOTH full 64-wide W_hh rows in regs (128 regs) and computes
// 2 complete dot products per step -> no reduction butterfly; gate exchange is
// two shfl_xor(width=2). Activations via MUFU.TANH. One __syncthreads/step
// spanning only 4 warps.

#define T_LEN 2048
#define HDIM  64
#define NCLS  10

#define FMA2(acc, a, b) \
    asm("fma.rn.f32x2 %0, %1, %2, %0;" : "+l"(acc) : "l"(a), "l"(b))
#define ADD2(d, a, b) \
    asm("add.rn.f32x2 %0, %1, %2;" : "=l"(d) : "l"(a), "l"(b))

__device__ __forceinline__ float tanh_fast(float z) {
    float r;
    asm("tanh.approx.f32 %0, %1;" : "=f"(r) : "f"(z));
    return r;
}

__device__ __forceinline__ float pair_sum(unsigned long long a) {
    return __uint_as_float((unsigned)a) + __uint_as_float((unsigned)(a >> 32));
}

__global__ __launch_bounds__(128, 3)
void lstm_net_kernel(const float* __restrict__ x,
                     const float* __restrict__ W_ih,
                     const float* __restrict__ W_hh,
                     const float* __restrict__ b_ih,
                     const float* __restrict__ b_hh,
                     const float* __restrict__ fc1_w,
                     const float* __restrict__ fc1_b,
                     const float* __restrict__ fc2_w,
                     const float* __restrict__ fc2_b,
                     float* __restrict__ out)
{
    __shared__ __align__(16) float sx[T_LEN];      // x row (8 KB)
    __shared__ __align__(16) float sh[2][HDIM];    // double-buffered hidden
    __shared__ __align__(16) float s1[HDIM];       // fc1 out

    const int b   = blockIdx.x;
    const int t   = threadIdx.x;
    const int hid = t >> 1;
    const int p   = t & 1;
    const int r0  = (2 * p) * HDIM + hid;          // i (p=0) / g (p=1)
    const int r1  = (2 * p + 1) * HDIM + hid;      // f (p=0) / o (p=1)

    // ---- stage x[b,:] (coalesced float4) ----
    {
        const float4* xr = reinterpret_cast<const float4*>(x + (size_t)b * T_LEN);
        float4* sx4 = reinterpret_cast<float4*>(sx);
        #pragma unroll
        for (int i = t; i < T_LEN / 4; i += 128) sx4[i] = xr[i];
    }

    // ---- both full W_hh rows -> 64 packed u64 regs (128 f32) ----
    unsigned long long w0[32], w1[32];
    {
        const ulonglong2* p0 = reinterpret_cast<const ulonglong2*>(W_hh + (size_t)r0 * HDIM);
        const ulonglong2* p1 = reinterpret_cast<const ulonglong2*>(W_hh + (size_t)r1 * HDIM);
        #pragma unroll
        for (int j = 0; j < 16; j++) {
            ulonglong2 v0 = p0[j];
            w0[2 * j] = v0.x;  w0[2 * j + 1] = v0.y;
            ulonglong2 v1 = p1[j];
            w1[2 * j] = v1.x;  w1[2 * j + 1] = v1.y;
        }
    }
    const float w_in0 = W_ih[r0];
    const float w_in1 = W_ih[r1];
    const float bias0 = b_ih[r0] + b_hh[r0];
    const float bias1 = b_ih[r1] + b_hh[r1];

    // row0 activation: p=0 -> sigmoid (i), p=1 -> tanh (g). row1 always sigmoid.
    const float zs0 = p ? 1.0f : 0.5f;
    const float aa0 = p ? 1.0f : 0.5f;
    const float ab0 = p ? 0.0f : 0.5f;

    if (t < HDIM) sh[0][t] = 0.0f;
    float c = 0.0f;
    __syncthreads();

    // one LSTM step: read sh[RB], write sh[RB^1]
    #define LSTM_STEP(RB, XT)                                                        \
    {                                                                                \
        const ulonglong2* hp = reinterpret_cast<const ulonglong2*>(sh[RB]);          \
        unsigned long long A0 = 0ull, A1 = 0ull, B0 = 0ull, B1 = 0ull;               \
        _Pragma("unroll")                                                            \
        for (int j = 0; j < 4; j++) {                                                \
            ulonglong2 h0 = hp[4 * j + 0], h1 = hp[4 * j + 1];                       \
            ulonglong2 h2 = hp[4 * j + 2], h3 = hp[4 * j + 3];                       \
            FMA2(A0, w0[8 * j + 0], h0.x);  FMA2(B0, w1[8 * j + 0], h0.x);           \
            FMA2(A1, w0[8 * j + 1], h0.y);  FMA2(B1, w1[8 * j + 1], h0.y);           \
            FMA2(A0, w0[8 * j + 2], h1.x);  FMA2(B0, w1[8 * j + 2], h1.x);           \
            FMA2(A1, w0[8 * j + 3], h1.y);  FMA2(B1, w1[8 * j + 3], h1.y);           \
            FMA2(A0, w0[8 * j + 4], h2.x);  FMA2(B0, w1[8 * j + 4], h2.x);           \
            FMA2(A1, w0[8 * j + 5], h2.y);  FMA2(B1, w1[8 * j + 5], h2.y);           \
            FMA2(A0, w0[8 * j + 6], h3.x);  FMA2(B0, w1[8 * j + 6], h3.x);           \
            FMA2(A1, w0[8 * j + 7], h3.y);  FMA2(B1, w1[8 * j + 7], h3.y);           \
        }                                                                            \
        unsigned long long As, Bs;                                                   \
        ADD2(As, A0, A1);  ADD2(Bs, B0, B1);                                         \
        float g0 = fmaf((XT), w_in0, bias0) + pair_sum(As);                          \
        float g1 = fmaf((XT), w_in1, bias1) + pair_sum(Bs);                          \
        float act0 = fmaf(tanh_fast(g0 * zs0), aa0, ab0);                            \
        float act1 = fmaf(tanh_fast(g1 * 0.5f), 0.5f, 0.5f);                         \
        float othA = __shfl_xor_sync(0xffffffffu, act0, 1, 2);                       \
        float othB = __shfl_xor_sync(0xffffffffu, act1, 1, 2);                       \
        float iv = p ? othA : act0;                                                  \
        float fv = p ? othB : act1;                                                  \
        float gv = p ? act0 : othA;                                                  \
        float ov = p ? act1 : othB;                                                  \
        c = fmaf(fv, c, iv * gv);                                                    \
        float hnew = ov * tanh_fast(c);                                              \
        if (p == 0) sh[(RB) ^ 1][hid] = hnew;                                        \
        __syncthreads();                                                             \
    }

    #pragma unroll 1
    for (int step = 0; step < T_LEN; step += 4) {
        const float4 xv = *reinterpret_cast<const float4*>(&sx[step]);
        LSTM_STEP(0, xv.x)
        LSTM_STEP(1, xv.y)
        LSTM_STEP(0, xv.z)
        LSTM_STEP(1, xv.w)
    }
    #undef LSTM_STEP

    // T_LEN % 4 == 0: final h lives in sh[0]
    const float* hf = sh[0];

    // ---- fc1 + relu (64 threads) ----
    if (t < HDIM) {
        float a = fc1_b[t];
        const float* wr = fc1_w + t * HDIM;
        #pragma unroll 16
        for (int k = 0; k < HDIM; k++) a = fmaf(wr[k], hf[k], a);
        s1[t] = fmaxf(a, 0.0f);
    }
    __syncthreads();

    // ---- fc2 (10 threads) ----
    if (t < NCLS) {
        float a = fc2_b[t];
        const float* wr = fc2_w + t * HDIM;
        #pragma unroll 16
        for (int k = 0; k < HDIM; k++) a = fmaf(wr[k], s1[k], a);
        out[(size_t)b * NCLS + t] = a;
    }
}

extern "C" void kernel_launch(void* const* d_in, const int* in_sizes, int n_in,
                              void* d_out, int out_size)
{
    const float* x     = (const float*)d_in[0];
    const float* W_ih  = (const float*)d_in[1];
    const float* W_hh  = (const float*)d_in[2];
    const float* b_ih  = (const float*)d_in[3];
    const float* b_hh  = (const float*)d_in[4];
    const float* fc1_w = (const float*)d_in[5];
    const float* fc1_b = (const float*)d_in[6];
    const float* fc2_w = (const float*)d_in[7];
    const float* fc2_b = (const float*)d_in[8];
    float* out = (float*)d_out;

    const int B = in_sizes[0] / T_LEN;   // 1024

    lstm_net_kernel<<<B, 128>>>(x, W_ih, W_hh, b_ih, b_hh,
                                fc1_w, fc1_b, fc2_w, fc2_b, out);
}